// round 1
// baseline (speedup 1.0000x reference)
#include <cuda_runtime.h>

// Problem dims (fixed by the reference)
#define Bn  4
#define Qn  256
#define KVn 1024
#define Hn  128
#define VSn 256

// Scratch for projected q and k (no cudaMalloc allowed)
__device__ float g_qp[Bn * Qn * Hn];    // [B*Q, H]
__device__ float g_kp[Bn * KVn * Hn];   // [B*KV, H]

// ---------------------------------------------------------------------------
// Kernel 1: project queries->g_qp and keys->g_kp.
// Each block handles 4 rows of one of the two GEMMs (row dims divisible by 4).
// 128 threads: thread t owns output column t. W column access is coalesced;
// input rows staged in smem and broadcast.
// ---------------------------------------------------------------------------
__global__ void proj_kernel(const float* __restrict__ queries,
                            const float* __restrict__ keys,
                            const float* __restrict__ Wq,
                            const float* __restrict__ Wk) {
    const int r0 = blockIdx.x * 4;
    const float* in;
    const float* W;
    float* outp;
    if (r0 < Bn * Qn) {
        in   = queries + r0 * Hn;
        W    = Wq;
        outp = g_qp + r0 * Hn;
    } else {
        const int rr = r0 - Bn * Qn;
        in   = keys + rr * Hn;
        W    = Wk;
        outp = g_kp + rr * Hn;
    }
    __shared__ float s[4][Hn];
    const int t = threadIdx.x;
    #pragma unroll
    for (int rr = 0; rr < 4; rr++) s[rr][t] = in[rr * Hn + t];
    __syncthreads();

    float a0 = 0.f, a1 = 0.f, a2 = 0.f, a3 = 0.f;
    #pragma unroll 8
    for (int kk = 0; kk < Hn; kk++) {
        const float w = W[kk * Hn + t];
        a0 = fmaf(s[0][kk], w, a0);
        a1 = fmaf(s[1][kk], w, a1);
        a2 = fmaf(s[2][kk], w, a2);
        a3 = fmaf(s[3][kk], w, a3);
    }
    outp[0 * Hn + t] = a0;
    outp[1 * Hn + t] = a1;
    outp[2 * Hn + t] = a2;
    outp[3 * Hn + t] = a3;
}

// ---------------------------------------------------------------------------
// Accurate-enough fast tanh: tanh(x) = sign(x) * (1 - 2/(1 + e^{2|x|}))
// ex2.approx + rcp.approx are each ~2^-22 rel err -> abs error < ~4e-7.
// Overflow-safe: large |x| -> ex2 = inf -> rcp = 0 -> tanh = sign(x)*1.
// Cost: 2 MUFU + 2 FADD/FFMA + 2 alu ops.
// ---------------------------------------------------------------------------
__device__ __forceinline__ float tanh_acc(float x) {
    const float ax = fabsf(x);
    float e;
    asm("ex2.approx.f32 %0, %1;" : "=f"(e) : "f"(ax * 2.885390081777927f)); // 2*log2(e)
    float r;
    asm("rcp.approx.f32 %0, %1;" : "=f"(r) : "f"(e + 1.0f));
    const float t = fmaf(-2.0f, r, 1.0f);
    return copysignf(t, x);
}

// ---------------------------------------------------------------------------
// Kernel 2: one block per (b, i) query row. 256 threads (8 warps).
// Pass 1: warp-per-key scores into smem (only j < valid_len).
// Pass 2: block softmax (max, exp, sum) exactly matching the -1e6 masking
//         semantics; valid_len == 0 degenerates to uniform weights over all KV.
// Pass 3: thread-per-output-column weighted sum of values.
// ---------------------------------------------------------------------------
__global__ void attn_kernel(const float* __restrict__ values,
                            const int* __restrict__ valid_lens,
                            const float* __restrict__ wv,
                            float* __restrict__ out) {
    const int row  = blockIdx.x;       // b*Qn + i
    const int b    = row >> 8;
    const int tid  = threadIdx.x;
    const int lane = tid & 31;
    const int warp = tid >> 5;

    __shared__ float s_sc[KVn];
    __shared__ float s_rmax[8];
    __shared__ float s_rsum[8];

    const int L     = valid_lens[b];
    const bool uni  = (L <= 0);        // all slots masked -> uniform softmax
    const int effL  = uni ? KVn : L;

    float Z;
    if (!uni) {
        // ---- Pass 1: scores ----
        const float4 q4 = *reinterpret_cast<const float4*>(&g_qp[row * Hn + lane * 4]);
        const float4 w4 = *reinterpret_cast<const float4*>(&wv[lane * 4]);
        const float* kb = g_kp + b * KVn * Hn;

        for (int j = warp; j < effL; j += 8) {
            const float4 k4 = *reinterpret_cast<const float4*>(&kb[j * Hn + lane * 4]);
            float s = w4.x * tanh_acc(q4.x + k4.x);
            s = fmaf(w4.y, tanh_acc(q4.y + k4.y), s);
            s = fmaf(w4.z, tanh_acc(q4.z + k4.z), s);
            s = fmaf(w4.w, tanh_acc(q4.w + k4.w), s);
            #pragma unroll
            for (int o = 16; o > 0; o >>= 1)
                s += __shfl_xor_sync(0xffffffffu, s, o);
            if (lane == 0) s_sc[j] = s;
        }
        __syncthreads();

        // ---- Pass 2a: block max over [0, effL) ----
        float m = -3.0e38f;
        for (int j = tid; j < effL; j += 256) m = fmaxf(m, s_sc[j]);
        #pragma unroll
        for (int o = 16; o > 0; o >>= 1)
            m = fmaxf(m, __shfl_xor_sync(0xffffffffu, m, o));
        if (lane == 0) s_rmax[warp] = m;
        __syncthreads();
        float M = s_rmax[0];
        #pragma unroll
        for (int k = 1; k < 8; k++) M = fmaxf(M, s_rmax[k]);

        // ---- Pass 2b: exp + sum ----
        float z = 0.f;
        for (int j = tid; j < effL; j += 256) {
            const float e = __expf(s_sc[j] - M);
            s_sc[j] = e;
            z += e;
        }
        #pragma unroll
        for (int o = 16; o > 0; o >>= 1)
            z += __shfl_xor_sync(0xffffffffu, z, o);
        if (lane == 0) s_rsum[warp] = z;
        __syncthreads();
        Z = s_rsum[0];
        #pragma unroll
        for (int k = 1; k < 8; k++) Z += s_rsum[k];
    } else {
        // valid_len == 0: reference gives softmax over all -1e6 -> uniform
        for (int j = tid; j < KVn; j += 256) s_sc[j] = 1.0f;
        __syncthreads();
        Z = (float)KVn;
    }

    // ---- Pass 3: AV. Thread tid owns output column tid. ----
    const int c = tid;
    const float* vb = values + (size_t)b * KVn * VSn + c;
    float a0 = 0.f, a1 = 0.f, a2 = 0.f, a3 = 0.f;
    int j = 0;
    for (; j + 4 <= effL; j += 4) {
        a0 = fmaf(s_sc[j + 0], vb[(j + 0) * VSn], a0);
        a1 = fmaf(s_sc[j + 1], vb[(j + 1) * VSn], a1);
        a2 = fmaf(s_sc[j + 2], vb[(j + 2) * VSn], a2);
        a3 = fmaf(s_sc[j + 3], vb[(j + 3) * VSn], a3);
    }
    for (; j < effL; j++) a0 = fmaf(s_sc[j], vb[j * VSn], a0);
    const float acc = (a0 + a1) + (a2 + a3);
    out[row * VSn + c] = acc / Z;
}

// ---------------------------------------------------------------------------
extern "C" void kernel_launch(void* const* d_in, const int* in_sizes, int n_in,
                              void* d_out, int out_size) {
    const float* queries = (const float*)d_in[0];
    const float* keys    = (const float*)d_in[1];
    const float* values  = (const float*)d_in[2];
    const int*   valid   = (const int*)d_in[3];
    const float* Wq      = (const float*)d_in[4];
    const float* Wk      = (const float*)d_in[5];
    const float* wv      = (const float*)d_in[6];
    float* out           = (float*)d_out;

    proj_kernel<<<(Bn * Qn + Bn * KVn) / 4, 128>>>(queries, keys, Wq, Wk);
    attn_kernel<<<Bn * Qn, 256>>>(values, valid, wv, out);
}